// round 15
// baseline (speedup 1.0000x reference)
#include <cuda_runtime.h>
#include <cuda_fp16.h>
#include <cstdint>

#define NGENES 978
#define BATCH  8192
#define NNODES (BATCH * NGENES)        /* 8,009,856 */
#define H1DIM  2048
#define OUTDIM 100
#define KPAD   1024                    /* GEMM1 K padded */
#define KPAD2  2048                    /* GEMM2 K (exact) */

// ---------------------------------------------------------------------------
// Scratch (allocation-free rule: __device__ globals)
// ---------------------------------------------------------------------------
__device__ float  g_agg[NNODES];                        // 32 MB
__device__ __half g_Ah[(size_t)BATCH * KPAD];           // 16 MB (h fp16)
__device__ __half g_Bh[(size_t)H1DIM * KPAD];           // 4 MB (W1^T fp16)
__device__ __half g_Ch[(size_t)BATCH * KPAD2];          // 32 MB (h1 fp16)
__device__ __half g_W2h[(size_t)128 * KPAD2];           // 0.5 MB (W2^T fp16)

__device__ __forceinline__ uint32_t smem_to_u32(const void* p) {
    uint32_t a;
    asm("{ .reg .u64 t; cvta.to.shared.u64 t, %1; cvt.u32.u64 %0, t; }"
        : "=r"(a) : "l"(p));
    return a;
}
#define SMEM_SWIZZLE_128B(off) ((off) ^ (((off) >> 3) & 0x70))

// ---------------------------------------------------------------------------
// family-generic tensor-core primitives (compute_103-safe)
// ---------------------------------------------------------------------------
__device__ __forceinline__ void ldsm_x4(uint32_t* r, uint32_t addr) {
    asm volatile("ldmatrix.sync.aligned.m8n8.x4.shared.b16 {%0,%1,%2,%3}, [%4];"
        : "=r"(r[0]), "=r"(r[1]), "=r"(r[2]), "=r"(r[3]) : "r"(addr));
}
__device__ __forceinline__ void mma_f16(float* c, const uint32_t* a,
                                        const uint32_t* b) {
    asm volatile(
        "mma.sync.aligned.m16n8k16.row.col.f32.f16.f16.f32 "
        "{%0,%1,%2,%3}, {%4,%5,%6,%7}, {%8,%9}, {%0,%1,%2,%3};"
        : "+f"(c[0]), "+f"(c[1]), "+f"(c[2]), "+f"(c[3])
        : "r"(a[0]), "r"(a[1]), "r"(a[2]), "r"(a[3]), "r"(b[0]), "r"(b[1]));
}
#define CP_ASYNC16(dst, src) \
    asm volatile("cp.async.cg.shared.global [%0], [%1], 16;" \
        :: "r"(dst), "l"(src) : "memory")
#define CP_COMMIT() asm volatile("cp.async.commit_group;" ::: "memory")
#define CP_WAIT(n)  asm volatile("cp.async.wait_group %0;" :: "n"(n) : "memory")

__device__ __forceinline__ uint32_t swz(uint32_t base, int row, int colb) {
    uint32_t off = (uint32_t)(row * 128 + colb);
    return base + (off ^ ((off >> 3) & 0x70));
}

// async-load one ROWS x 64-half tile (128B rows) into SW128 SMEM
template <int ROWS>
__device__ __forceinline__ void load_tile_async(uint32_t dst,
                                                const uint4* __restrict__ g,
                                                int rowbase, int c, int tid,
                                                int stride_u4) {
#pragma unroll
    for (int it = 0; it < ROWS / 32; ++it) {
        int pos = tid + it * 256;
        int r = pos >> 3;
        int j = pos & 7;
        const uint4* src = &g[(size_t)(rowbase + r) * stride_u4 + c * 8 + j];
        uint32_t off = SMEM_SWIZZLE_128B((uint32_t)(r * 128 + j * 16));
        CP_ASYNC16(dst + off, src);
    }
}

// ---------------------------------------------------------------------------
// 1) zero accumulator (8 floats/thread)
// ---------------------------------------------------------------------------
__global__ void zero_agg_kernel() {
    size_t i = ((size_t)blockIdx.x * blockDim.x + threadIdx.x) * 2;
    size_t n4 = NNODES / 4;                          // 2,002,464 (exact)
    float4 z = make_float4(0.f, 0.f, 0.f, 0.f);
    if (i < n4)     reinterpret_cast<float4*>(g_agg)[i]     = z;
    if (i + 1 < n4) reinterpret_cast<float4*>(g_agg)[i + 1] = z;
}

// ---------------------------------------------------------------------------
// 2) edge scatter: agg[dst] += x[src] * w   (int32 edges, 16/thread)
// ---------------------------------------------------------------------------
__global__ void scatter_kernel(const int* __restrict__ edges,
                               const float* __restrict__ x,
                               const float* __restrict__ gw,
                               long long E) {
    long long i = ((long long)blockIdx.x * blockDim.x + threadIdx.x) * 16;
    if (i >= E) return;
    float w = __ldg(gw);
    if (i + 15 < E) {
        int4 s[4], d[4];
#pragma unroll
        for (int q = 0; q < 4; ++q) {
            s[q] = __ldcs(reinterpret_cast<const int4*>(edges + i + 4 * q));
            d[q] = __ldcs(reinterpret_cast<const int4*>(edges + E + i + 4 * q));
        }
#pragma unroll
        for (int q = 0; q < 4; ++q) {
            float v0 = __ldg(x + s[q].x) * w;
            float v1 = __ldg(x + s[q].y) * w;
            float v2 = __ldg(x + s[q].z) * w;
            float v3 = __ldg(x + s[q].w) * w;
            atomicAdd(&g_agg[d[q].x], v0);
            atomicAdd(&g_agg[d[q].y], v1);
            atomicAdd(&g_agg[d[q].z], v2);
            atomicAdd(&g_agg[d[q].w], v3);
        }
    } else {
        for (long long j = i; j < E; ++j) {
            int s = __ldcs(edges + j);
            int d = __ldcs(edges + E + j);
            atomicAdd(&g_agg[d], __ldg(x + s) * w);
        }
    }
}

// ---------------------------------------------------------------------------
// 3) fused: h = relu(agg + b) -> fp16 (4 elems/thread; 2x float2 loads —
//    float4 unsafe: 978 % 4 == 2 makes odd-row bases only 8B-aligned)
// ---------------------------------------------------------------------------
__global__ void convA_kernel(const float* __restrict__ gb) {
    size_t q = (size_t)blockIdx.x * blockDim.x + threadIdx.x;
    if (q >= (size_t)BATCH * KPAD / 4) return;
    int row = (int)(q >> 8);             // KPAD/4 = 256 quads per row
    int kq  = (int)((q & 255) << 2);     // 0, 4, ..., 1020
    float v0 = 0.f, v1 = 0.f, v2 = 0.f, v3 = 0.f;
    if (kq < NGENES) {
        float b = __ldg(gb);
        const float* a = g_agg + (size_t)row * NGENES + kq;
        float2 p0 = *reinterpret_cast<const float2*>(a);
        v0 = fmaxf(p0.x + b, 0.f);
        v1 = fmaxf(p0.y + b, 0.f);
        if (kq + 3 < NGENES) {           // kq == 976 is the only partial quad
            float2 p1 = *reinterpret_cast<const float2*>(a + 2);
            v2 = fmaxf(p1.x + b, 0.f);
            v3 = fmaxf(p1.y + b, 0.f);
        }
    }
    __half2 h0, h1;
    h0.x = __float2half(v0); h0.y = __float2half(v1);
    h1.x = __float2half(v2); h1.y = __float2half(v3);
    __half2* dst = reinterpret_cast<__half2*>(g_Ah + ((size_t)row << 10) + kq);
    dst[0] = h0;
    dst[1] = h1;
}

// ---------------------------------------------------------------------------
// 4) smem-tiled transpose+convert: out[n][KP] (half) = in[k][N_in] (f32)
// ---------------------------------------------------------------------------
__global__ void transpose_half_kernel(const float* __restrict__ in,
                                      __half* __restrict__ out,
                                      int K_in, int N_in, int KP) {
    __shared__ float t[32][33];
    const int k0 = blockIdx.y * 32;
    const int n0 = blockIdx.x * 32;
    const int tx = threadIdx.x;      // 0..31
    const int ty = threadIdx.y;      // 0..7
#pragma unroll
    for (int r = 0; r < 4; ++r) {
        int k = k0 + ty + r * 8;
        int n = n0 + tx;
        t[ty + r * 8][tx] = (k < K_in && n < N_in)
                          ? in[(size_t)k * N_in + n] : 0.f;
    }
    __syncthreads();
#pragma unroll
    for (int r = 0; r < 4; ++r) {
        int n = n0 + ty + r * 8;
        int k = k0 + tx;
        out[(size_t)n * KP + k] = __float2half(t[tx][ty + r * 8]);
    }
}

// ---------------------------------------------------------------------------
// 5) HMMA GEMM1 (fp16 single-pass): h1 = relu( h @ W1 + b1 ) -> fp16
//    CTA 128x128, warp tile 64x32, Kc=64 chunks, cp.async double buffer.
// ---------------------------------------------------------------------------
#define KCHUNK      64
#define NCHUNKS     (KPAD / KCHUNK)            /* 16 */
#define TILE_BYTES  (128 * 128)                /* 16 KB */
#define STAGE_BYTES (2 * TILE_BYTES)           /* Ah, Bh = 32 KB */
#define SMEM_TOTAL_G (2 * STAGE_BYTES)         /* 65536 B */

__global__ void __launch_bounds__(256, 1)
tc_gemm1_kernel(const float* __restrict__ bias) {
    extern __shared__ char smem[];
    const uint32_t sb = smem_to_u32(smem);
    const int tid  = threadIdx.x;
    const int wid  = tid >> 5;
    const int lane = tid & 31;
    const int bm = blockIdx.y * 128;
    const int bn = blockIdx.x * 128;
    const int wm = wid & 1;
    const int wn = wid >> 1;

    const uint4* gAh = reinterpret_cast<const uint4*>(g_Ah);
    const uint4* gBh = reinterpret_cast<const uint4*>(g_Bh);

    float acc[4][4][4];
#pragma unroll
    for (int i = 0; i < 4; ++i)
#pragma unroll
        for (int j = 0; j < 4; ++j)
#pragma unroll
            for (int r = 0; r < 4; ++r) acc[i][j][r] = 0.f;

    const int a_row = (lane & 15);
    const int a_kb  = (lane >> 4) * 16;
    const int b_row = (lane & 7) + ((lane >> 4) & 1) * 8;
    const int b_kb  = ((lane >> 3) & 1) * 16;

    load_tile_async<128>(sb + 0 * TILE_BYTES, gAh, bm, 0, tid, KPAD / 8);
    load_tile_async<128>(sb + 1 * TILE_BYTES, gBh, bn, 0, tid, KPAD / 8);
    CP_COMMIT();

    for (int c = 0; c < NCHUNKS; ++c) {
        const uint32_t cur = sb + (uint32_t)(c & 1) * STAGE_BYTES;
        if (c + 1 < NCHUNKS) {
            const uint32_t nxt = sb + (uint32_t)((c + 1) & 1) * STAGE_BYTES;
            load_tile_async<128>(nxt + 0 * TILE_BYTES, gAh, bm, c + 1, tid, KPAD / 8);
            load_tile_async<128>(nxt + 1 * TILE_BYTES, gBh, bn, c + 1, tid, KPAD / 8);
            CP_COMMIT();
            CP_WAIT(1);
        } else {
            CP_WAIT(0);
        }
        __syncthreads();

        const uint32_t sAh = cur + 0 * TILE_BYTES;
        const uint32_t sBh = cur + 1 * TILE_BYTES;

#pragma unroll
        for (int kk = 0; kk < 4; ++kk) {
            const int kbyte = kk * 32;
            uint32_t Ah[4][4];
#pragma unroll
            for (int mb = 0; mb < 4; ++mb) {
                const int row = wm * 64 + mb * 16 + a_row;
                ldsm_x4(Ah[mb], swz(sAh, row, kbyte + a_kb));
            }
            uint32_t Bh[4][2];
#pragma unroll
            for (int pb = 0; pb < 2; ++pb) {
                const int row = wn * 32 + pb * 16 + b_row;
                uint32_t t[4];
                ldsm_x4(t, swz(sBh, row, kbyte + b_kb));
                Bh[2 * pb][0] = t[0]; Bh[2 * pb][1] = t[1];
                Bh[2 * pb + 1][0] = t[2]; Bh[2 * pb + 1][1] = t[3];
            }
#pragma unroll
            for (int mb = 0; mb < 4; ++mb)
#pragma unroll
                for (int nb = 0; nb < 4; ++nb)
                    mma_f16(acc[mb][nb], Ah[mb], Bh[nb]);
        }
        __syncthreads();
    }

    // epilogue: bias + relu, emit fp16 h1
#pragma unroll
    for (int mb = 0; mb < 4; ++mb) {
        const int m0 = bm + wm * 64 + mb * 16 + (lane >> 2);
#pragma unroll
        for (int nb = 0; nb < 4; ++nb) {
            const int n0 = bn + wn * 32 + nb * 8 + 2 * (lane & 3);
            const float b0 = __ldg(&bias[n0]);
            const float b1 = __ldg(&bias[n0 + 1]);
#pragma unroll
            for (int h = 0; h < 2; ++h) {
                const int m = m0 + h * 8;
                float x0 = fmaxf(acc[mb][nb][2 * h + 0] + b0, 0.f);
                float x1 = fmaxf(acc[mb][nb][2 * h + 1] + b1, 0.f);
                __half2 hv;
                hv.x = __float2half(x0);
                hv.y = __float2half(x1);
                reinterpret_cast<__half2*>(g_Ch)[((size_t)m * KPAD2 + n0) / 2] = hv;
            }
        }
    }
}

// ---------------------------------------------------------------------------
// 6) HMMA GEMM2 (fp16 single-pass): out[8192,100] = h1 @ W2 + b2
//    CTA 64x128, warp tile 32x32, Kc=64, 32 chunks, double buffer.
// ---------------------------------------------------------------------------
#define TILE_A2     (64 * 128)                 /* 8 KB  */
#define TILE_B2     (128 * 128)                /* 16 KB */
#define STAGE2      (TILE_A2 + TILE_B2)        /* 24 KB */
#define SMEM_TOTAL_G2 (2 * STAGE2)             /* 49152 B */
#define NCHUNKS2    (KPAD2 / KCHUNK)           /* 32 */

__global__ void __launch_bounds__(256, 1)
tc_gemm2_kernel(const float* __restrict__ bias, float* __restrict__ C) {
    extern __shared__ char smem[];
    const uint32_t sb = smem_to_u32(smem);
    const int tid  = threadIdx.x;
    const int wid  = tid >> 5;
    const int lane = tid & 31;
    const int bm = blockIdx.y * 64;
    const int wm = wid & 1;    // 2 x 32 rows
    const int wn = wid >> 1;   // 4 x 32 cols

    const uint4* gAh = reinterpret_cast<const uint4*>(g_Ch);
    const uint4* gBh = reinterpret_cast<const uint4*>(g_W2h);

    float acc[2][4][4];
#pragma unroll
    for (int i = 0; i < 2; ++i)
#pragma unroll
        for (int j = 0; j < 4; ++j)
#pragma unroll
            for (int r = 0; r < 4; ++r) acc[i][j][r] = 0.f;

    const int a_row = (lane & 15);
    const int a_kb  = (lane >> 4) * 16;
    const int b_row = (lane & 7) + ((lane >> 4) & 1) * 8;
    const int b_kb  = ((lane >> 3) & 1) * 16;

    load_tile_async<64>(sb + 0, gAh, bm, 0, tid, KPAD2 / 8);
    load_tile_async<128>(sb + TILE_A2, gBh, 0, 0, tid, KPAD2 / 8);
    CP_COMMIT();

    for (int c = 0; c < NCHUNKS2; ++c) {
        const uint32_t cur = sb + (uint32_t)(c & 1) * STAGE2;
        if (c + 1 < NCHUNKS2) {
            const uint32_t nxt = sb + (uint32_t)((c + 1) & 1) * STAGE2;
            load_tile_async<64>(nxt + 0, gAh, bm, c + 1, tid, KPAD2 / 8);
            load_tile_async<128>(nxt + TILE_A2, gBh, 0, c + 1, tid, KPAD2 / 8);
            CP_COMMIT();
            CP_WAIT(1);
        } else {
            CP_WAIT(0);
        }
        __syncthreads();

        const uint32_t sAh = cur + 0;
        const uint32_t sBh = cur + TILE_A2;

#pragma unroll
        for (int kk = 0; kk < 4; ++kk) {
            const int kbyte = kk * 32;
            uint32_t Ah[2][4];
#pragma unroll
            for (int mb = 0; mb < 2; ++mb) {
                const int row = wm * 32 + mb * 16 + a_row;
                ldsm_x4(Ah[mb], swz(sAh, row, kbyte + a_kb));
            }
            uint32_t Bh[4][2];
#pragma unroll
            for (int pb = 0; pb < 2; ++pb) {
                const int row = wn * 32 + pb * 16 + b_row;
                uint32_t t[4];
                ldsm_x4(t, swz(sBh, row, kbyte + b_kb));
                Bh[2 * pb][0] = t[0]; Bh[2 * pb][1] = t[1];
                Bh[2 * pb + 1][0] = t[2]; Bh[2 * pb + 1][1] = t[3];
            }
#pragma unroll
            for (int mb = 0; mb < 2; ++mb)
#pragma unroll
                for (int nb = 0; nb < 4; ++nb)
                    mma_f16(acc[mb][nb], Ah[mb], Bh[nb]);
        }
        __syncthreads();
    }

    // epilogue: bias, write f32 out, guard n < 100
#pragma unroll
    for (int mb = 0; mb < 2; ++mb) {
        const int m0 = bm + wm * 32 + mb * 16 + (lane >> 2);
#pragma unroll
        for (int nb = 0; nb < 4; ++nb) {
            const int n0 = wn * 32 + nb * 8 + 2 * (lane & 3);
            if (n0 < OUTDIM) {
                const float b0 = __ldg(&bias[n0]);
                const float b1 = __ldg(&bias[n0 + 1]);
                float2 v0, v1;
                v0.x = acc[mb][nb][0] + b0;
                v0.y = acc[mb][nb][1] + b1;
                v1.x = acc[mb][nb][2] + b0;
                v1.y = acc[mb][nb][3] + b1;
                *reinterpret_cast<float2*>(C + (size_t)m0 * OUTDIM + n0)       = v0;
                *reinterpret_cast<float2*>(C + (size_t)(m0 + 8) * OUTDIM + n0) = v1;
            }
        }
    }
}

// ---------------------------------------------------------------------------
// launch
// ---------------------------------------------------------------------------
extern "C" void kernel_launch(void* const* d_in, const int* in_sizes, int n_in,
                              void* d_out, int out_size) {
    const float* inputs = (const float*)d_in[0];      // [8192, 978] f32
    const int*   edges  = (const int*)d_in[1];        // [2, E] int32
    const float* gw     = (const float*)d_in[2];      // [1,1]
    const float* gb     = (const float*)d_in[3];      // [1]
    const float* W1     = (const float*)d_in[4];      // [978, 2048]
    const float* b1     = (const float*)d_in[5];      // [2048]
    const float* W2     = (const float*)d_in[6];      // [2048, 100]
    const float* b2     = (const float*)d_in[7];      // [100]
    float*       out    = (float*)d_out;              // [8192, 100]

    const long long E = (long long)in_sizes[1] / 2;   // 20,000,000

    __half *Bh, *W2h;
    cudaGetSymbolAddress((void**)&Bh, g_Bh);
    cudaGetSymbolAddress((void**)&W2h, g_W2h);

    cudaFuncSetAttribute(tc_gemm1_kernel,
                         cudaFuncAttributeMaxDynamicSharedMemorySize, SMEM_TOTAL_G);
    cudaFuncSetAttribute(tc_gemm2_kernel,
                         cudaFuncAttributeMaxDynamicSharedMemorySize, SMEM_TOTAL_G2);

    // 1) zero accumulator (8 floats/thread)
    {
        size_t pairs = (NNODES / 4 + 1) / 2;
        zero_agg_kernel<<<(int)((pairs + 255) / 256), 256>>>();
    }
    // 2) edge scatter (16 edges/thread)
    {
        long long threads_needed = (E + 15) / 16;
        int blocks = (int)((threads_needed + 255) / 256);
        scatter_kernel<<<blocks, 256>>>(edges, inputs, gw, E);
    }
    // 3) h = relu(agg + b) -> fp16 (4 elems/thread)
    {
        size_t n = (size_t)BATCH * KPAD / 4;
        convA_kernel<<<(int)((n + 255) / 256), 256>>>(gb);
    }
    // 4) W1^T -> fp16 [2048,1024]; W2^T -> fp16 [128,2048] (tiled transpose)
    {
        dim3 blk(32, 8);
        dim3 g1(H1DIM / 32, KPAD / 32);
        transpose_half_kernel<<<g1, blk>>>(W1, Bh, NGENES, H1DIM, KPAD);
        dim3 g2(128 / 32, KPAD2 / 32);
        transpose_half_kernel<<<g2, blk>>>(W2, W2h, KPAD2, OUTDIM, KPAD2);
    }
    // 5) h1 = relu(h @ W1 + b1) -> fp16 (fused epilogue)
    {
        dim3 grid(H1DIM / 128, BATCH / 128);
        tc_gemm1_kernel<<<grid, 256, SMEM_TOTAL_G>>>(b1);
    }
    // 6) out = h1 @ W2 + b2 on HMMA (single-pass)
    {
        dim3 grid(1, BATCH / 64);
        tc_gemm2_kernel<<<grid, 256, SMEM_TOTAL_G2>>>(b2, out);
    }
}

// round 17
// speedup vs baseline: 1.0513x; 1.0513x over previous
#include <cuda_runtime.h>
#include <cuda_fp16.h>
#include <cstdint>

#define NGENES 978
#define BATCH  8192
#define NNODES (BATCH * NGENES)        /* 8,009,856 */
#define H1DIM  2048
#define OUTDIM 100
#define KPAD   1024                    /* GEMM1 K padded */
#define KPAD2  2048                    /* GEMM2 K (exact) */

// ---------------------------------------------------------------------------
// Scratch (allocation-free rule: __device__ globals)
// ---------------------------------------------------------------------------
__device__ float  g_agg[NNODES];                        // 32 MB
__device__ __half g_Ah[(size_t)BATCH * KPAD];           // 16 MB (h fp16)
__device__ __half g_Bh[(size_t)H1DIM * KPAD];           // 4 MB (W1^T fp16)
__device__ __half g_Ch[(size_t)BATCH * KPAD2];          // 32 MB (h1 fp16)
__device__ __half g_W2h[(size_t)128 * KPAD2];           // 0.5 MB (W2^T fp16)

__device__ __forceinline__ uint32_t smem_to_u32(const void* p) {
    uint32_t a;
    asm("{ .reg .u64 t; cvta.to.shared.u64 t, %1; cvt.u32.u64 %0, t; }"
        : "=r"(a) : "l"(p));
    return a;
}
#define SMEM_SWIZZLE_128B(off) ((off) ^ (((off) >> 3) & 0x70))

// ---------------------------------------------------------------------------
// family-generic tensor-core primitives (compute_103-safe)
// ---------------------------------------------------------------------------
__device__ __forceinline__ void ldsm_x4(uint32_t* r, uint32_t addr) {
    asm volatile("ldmatrix.sync.aligned.m8n8.x4.shared.b16 {%0,%1,%2,%3}, [%4];"
        : "=r"(r[0]), "=r"(r[1]), "=r"(r[2]), "=r"(r[3]) : "r"(addr));
}
__device__ __forceinline__ void mma_f16(float* c, const uint32_t* a,
                                        const uint32_t* b) {
    asm volatile(
        "mma.sync.aligned.m16n8k16.row.col.f32.f16.f16.f32 "
        "{%0,%1,%2,%3}, {%4,%5,%6,%7}, {%8,%9}, {%0,%1,%2,%3};"
        : "+f"(c[0]), "+f"(c[1]), "+f"(c[2]), "+f"(c[3])
        : "r"(a[0]), "r"(a[1]), "r"(a[2]), "r"(a[3]), "r"(b[0]), "r"(b[1]));
}
#define CP_ASYNC16(dst, src) \
    asm volatile("cp.async.cg.shared.global [%0], [%1], 16;" \
        :: "r"(dst), "l"(src) : "memory")
#define CP_COMMIT() asm volatile("cp.async.commit_group;" ::: "memory")
#define CP_WAIT(n)  asm volatile("cp.async.wait_group %0;" :: "n"(n) : "memory")

__device__ __forceinline__ uint32_t swz(uint32_t base, int row, int colb) {
    uint32_t off = (uint32_t)(row * 128 + colb);
    return base + (off ^ ((off >> 3) & 0x70));
}

// async-load one ROWS x 64-half tile (128B rows) into SW128 SMEM
template <int ROWS>
__device__ __forceinline__ void load_tile_async(uint32_t dst,
                                                const uint4* __restrict__ g,
                                                int rowbase, int c, int tid,
                                                int stride_u4) {
#pragma unroll
    for (int it = 0; it < ROWS / 32; ++it) {
        int pos = tid + it * 256;
        int r = pos >> 3;
        int j = pos & 7;
        const uint4* src = &g[(size_t)(rowbase + r) * stride_u4 + c * 8 + j];
        uint32_t off = SMEM_SWIZZLE_128B((uint32_t)(r * 128 + j * 16));
        CP_ASYNC16(dst + off, src);
    }
}

// ---------------------------------------------------------------------------
// 1) zero accumulator (4 floats/thread)
// ---------------------------------------------------------------------------
__global__ void zero_agg_kernel() {
    size_t i = (size_t)blockIdx.x * blockDim.x + threadIdx.x;
    size_t n4 = NNODES / 4;
    if (i < n4) reinterpret_cast<float4*>(g_agg)[i] = make_float4(0.f, 0.f, 0.f, 0.f);
}

// ---------------------------------------------------------------------------
// 2) edge scatter: agg[dst] += x[src] * w   (int32 edges, 8/thread)
// ---------------------------------------------------------------------------
__global__ void scatter_kernel(const int* __restrict__ edges,
                               const float* __restrict__ x,
                               const float* __restrict__ gw,
                               long long E) {
    long long i = ((long long)blockIdx.x * blockDim.x + threadIdx.x) * 8;
    if (i >= E) return;
    float w = __ldg(gw);
    if (i + 7 < E) {
        int4 s0 = __ldcs(reinterpret_cast<const int4*>(edges + i));
        int4 s1 = __ldcs(reinterpret_cast<const int4*>(edges + i + 4));
        int4 d0 = __ldcs(reinterpret_cast<const int4*>(edges + E + i));
        int4 d1 = __ldcs(reinterpret_cast<const int4*>(edges + E + i + 4));
        float v0 = __ldg(x + s0.x) * w;
        float v1 = __ldg(x + s0.y) * w;
        float v2 = __ldg(x + s0.z) * w;
        float v3 = __ldg(x + s0.w) * w;
        float v4 = __ldg(x + s1.x) * w;
        float v5 = __ldg(x + s1.y) * w;
        float v6 = __ldg(x + s1.z) * w;
        float v7 = __ldg(x + s1.w) * w;
        atomicAdd(&g_agg[d0.x], v0);
        atomicAdd(&g_agg[d0.y], v1);
        atomicAdd(&g_agg[d0.z], v2);
        atomicAdd(&g_agg[d0.w], v3);
        atomicAdd(&g_agg[d1.x], v4);
        atomicAdd(&g_agg[d1.y], v5);
        atomicAdd(&g_agg[d1.z], v6);
        atomicAdd(&g_agg[d1.w], v7);
    } else {
        for (long long j = i; j < E; ++j) {
            int s = __ldcs(edges + j);
            int d = __ldcs(edges + E + j);
            atomicAdd(&g_agg[d], __ldg(x + s) * w);
        }
    }
}

// ---------------------------------------------------------------------------
// 3) fused: h = relu(agg + b) -> fp16 (half2 pairs; 978 even, no straddle)
// ---------------------------------------------------------------------------
__global__ void convA_kernel(const float* __restrict__ gb) {
    size_t p = (size_t)blockIdx.x * blockDim.x + threadIdx.x;
    if (p >= (size_t)BATCH * KPAD / 2) return;
    int row = (int)(p >> 9);
    int kp  = (int)((p & 511) << 1);
    __half2 hv = __float2half2_rn(0.f);
    if (kp < NGENES) {
        float b = __ldg(gb);
        const float* a = g_agg + (size_t)row * NGENES + kp;
        float v0 = fmaxf(a[0] + b, 0.f);
        float v1 = fmaxf(a[1] + b, 0.f);
        hv.x = __float2half(v0);
        hv.y = __float2half(v1);
    }
    reinterpret_cast<__half2*>(g_Ah)[((size_t)row << 9) + (kp >> 1)] = hv;
}

// ---------------------------------------------------------------------------
// 4) merged transpose+convert for BOTH weights in ONE launch.
//    Job 0 (blocks [0, NB1)):  W1 [978, 2048]  -> g_Bh  [2048, KPAD]
//    Job 1 (blocks [NB1, NB1+NB2)): W2 [2048, 100] -> g_W2h [128, KPAD2]
// ---------------------------------------------------------------------------
#define NB1_X (H1DIM / 32)      /* 64 */
#define NB1_Y (KPAD / 32)       /* 32 */
#define NB1   (NB1_X * NB1_Y)   /* 2048 */
#define NB2_X (128 / 32)        /* 4 */
#define NB2_Y (KPAD2 / 32)      /* 64 */
#define NB2   (NB2_X * NB2_Y)   /* 256 */

__global__ void transpose_both_kernel(const float* __restrict__ W1,
                                      const float* __restrict__ W2) {
    __shared__ float t[32][33];
    const int b = blockIdx.x;
    const float* in;
    __half* out;
    int K_in, N_in, KP, bx, by;
    if (b < NB1) {
        in = W1; out = g_Bh; K_in = NGENES; N_in = H1DIM; KP = KPAD;
        bx = b % NB1_X; by = b / NB1_X;
    } else {
        in = W2; out = g_W2h; K_in = KPAD2; N_in = OUTDIM; KP = KPAD2;
        int b2 = b - NB1;
        bx = b2 % NB2_X; by = b2 / NB2_X;
    }
    const int k0 = by * 32;
    const int n0 = bx * 32;
    const int tx = threadIdx.x;      // 0..31
    const int ty = threadIdx.y;      // 0..7
#pragma unroll
    for (int r = 0; r < 4; ++r) {
        int k = k0 + ty + r * 8;
        int n = n0 + tx;
        t[ty + r * 8][tx] = (k < K_in && n < N_in)
                          ? in[(size_t)k * N_in + n] : 0.f;
    }
    __syncthreads();
#pragma unroll
    for (int r = 0; r < 4; ++r) {
        int n = n0 + ty + r * 8;
        int k = k0 + tx;
        out[(size_t)n * KP + k] = __float2half(t[tx][ty + r * 8]);
    }
}

// ---------------------------------------------------------------------------
// 5) HMMA GEMM1 (fp16 single-pass): h1 = relu( h @ W1 + b1 ) -> fp16
//    CTA 128x128, warp tile 64x32, Kc=64 chunks, cp.async double buffer.
// ---------------------------------------------------------------------------
#define KCHUNK      64
#define NCHUNKS     (KPAD / KCHUNK)            /* 16 */
#define TILE_BYTES  (128 * 128)                /* 16 KB */
#define STAGE_BYTES (2 * TILE_BYTES)           /* Ah, Bh = 32 KB */
#define SMEM_TOTAL_G (2 * STAGE_BYTES)         /* 65536 B */

__global__ void __launch_bounds__(256, 1)
tc_gemm1_kernel(const float* __restrict__ bias) {
    extern __shared__ char smem[];
    const uint32_t sb = smem_to_u32(smem);
    const int tid  = threadIdx.x;
    const int wid  = tid >> 5;
    const int lane = tid & 31;
    const int bm = blockIdx.y * 128;
    const int bn = blockIdx.x * 128;
    const int wm = wid & 1;
    const int wn = wid >> 1;

    const uint4* gAh = reinterpret_cast<const uint4*>(g_Ah);
    const uint4* gBh = reinterpret_cast<const uint4*>(g_Bh);

    float acc[4][4][4];
#pragma unroll
    for (int i = 0; i < 4; ++i)
#pragma unroll
        for (int j = 0; j < 4; ++j)
#pragma unroll
            for (int r = 0; r < 4; ++r) acc[i][j][r] = 0.f;

    const int a_row = (lane & 15);
    const int a_kb  = (lane >> 4) * 16;
    const int b_row = (lane & 7) + ((lane >> 4) & 1) * 8;
    const int b_kb  = ((lane >> 3) & 1) * 16;

    load_tile_async<128>(sb + 0 * TILE_BYTES, gAh, bm, 0, tid, KPAD / 8);
    load_tile_async<128>(sb + 1 * TILE_BYTES, gBh, bn, 0, tid, KPAD / 8);
    CP_COMMIT();

    for (int c = 0; c < NCHUNKS; ++c) {
        const uint32_t cur = sb + (uint32_t)(c & 1) * STAGE_BYTES;
        if (c + 1 < NCHUNKS) {
            const uint32_t nxt = sb + (uint32_t)((c + 1) & 1) * STAGE_BYTES;
            load_tile_async<128>(nxt + 0 * TILE_BYTES, gAh, bm, c + 1, tid, KPAD / 8);
            load_tile_async<128>(nxt + 1 * TILE_BYTES, gBh, bn, c + 1, tid, KPAD / 8);
            CP_COMMIT();
            CP_WAIT(1);
        } else {
            CP_WAIT(0);
        }
        __syncthreads();

        const uint32_t sAh = cur + 0 * TILE_BYTES;
        const uint32_t sBh = cur + 1 * TILE_BYTES;

#pragma unroll
        for (int kk = 0; kk < 4; ++kk) {
            const int kbyte = kk * 32;
            uint32_t Ah[4][4];
#pragma unroll
            for (int mb = 0; mb < 4; ++mb) {
                const int row = wm * 64 + mb * 16 + a_row;
                ldsm_x4(Ah[mb], swz(sAh, row, kbyte + a_kb));
            }
            uint32_t Bh[4][2];
#pragma unroll
            for (int pb = 0; pb < 2; ++pb) {
                const int row = wn * 32 + pb * 16 + b_row;
                uint32_t t[4];
                ldsm_x4(t, swz(sBh, row, kbyte + b_kb));
                Bh[2 * pb][0] = t[0]; Bh[2 * pb][1] = t[1];
                Bh[2 * pb + 1][0] = t[2]; Bh[2 * pb + 1][1] = t[3];
            }
#pragma unroll
            for (int mb = 0; mb < 4; ++mb)
#pragma unroll
                for (int nb = 0; nb < 4; ++nb)
                    mma_f16(acc[mb][nb], Ah[mb], Bh[nb]);
        }
        __syncthreads();
    }

    // epilogue: bias + relu, emit fp16 h1
#pragma unroll
    for (int mb = 0; mb < 4; ++mb) {
        const int m0 = bm + wm * 64 + mb * 16 + (lane >> 2);
#pragma unroll
        for (int nb = 0; nb < 4; ++nb) {
            const int n0 = bn + wn * 32 + nb * 8 + 2 * (lane & 3);
            const float b0 = __ldg(&bias[n0]);
            const float b1 = __ldg(&bias[n0 + 1]);
#pragma unroll
            for (int h = 0; h < 2; ++h) {
                const int m = m0 + h * 8;
                float x0 = fmaxf(acc[mb][nb][2 * h + 0] + b0, 0.f);
                float x1 = fmaxf(acc[mb][nb][2 * h + 1] + b1, 0.f);
                __half2 hv;
                hv.x = __float2half(x0);
                hv.y = __float2half(x1);
                reinterpret_cast<__half2*>(g_Ch)[((size_t)m * KPAD2 + n0) / 2] = hv;
            }
        }
    }
}

// ---------------------------------------------------------------------------
// 6) HMMA GEMM2 (fp16 single-pass): out[8192,100] = h1 @ W2 + b2
//    CTA 64x128, warp tile 32x32, Kc=64, 32 chunks, double buffer.
// ---------------------------------------------------------------------------
#define TILE_A2     (64 * 128)                 /* 8 KB  */
#define TILE_B2     (128 * 128)                /* 16 KB */
#define STAGE2      (TILE_A2 + TILE_B2)        /* 24 KB */
#define SMEM_TOTAL_G2 (2 * STAGE2)             /* 49152 B */
#define NCHUNKS2    (KPAD2 / KCHUNK)           /* 32 */

__global__ void __launch_bounds__(256, 1)
tc_gemm2_kernel(const float* __restrict__ bias, float* __restrict__ C) {
    extern __shared__ char smem[];
    const uint32_t sb = smem_to_u32(smem);
    const int tid  = threadIdx.x;
    const int wid  = tid >> 5;
    const int lane = tid & 31;
    const int bm = blockIdx.y * 64;
    const int wm = wid & 1;    // 2 x 32 rows
    const int wn = wid >> 1;   // 4 x 32 cols

    const uint4* gAh = reinterpret_cast<const uint4*>(g_Ch);
    const uint4* gBh = reinterpret_cast<const uint4*>(g_W2h);

    float acc[2][4][4];
#pragma unroll
    for (int i = 0; i < 2; ++i)
#pragma unroll
        for (int j = 0; j < 4; ++j)
#pragma unroll
            for (int r = 0; r < 4; ++r) acc[i][j][r] = 0.f;

    const int a_row = (lane & 15);
    const int a_kb  = (lane >> 4) * 16;
    const int b_row = (lane & 7) + ((lane >> 4) & 1) * 8;
    const int b_kb  = ((lane >> 3) & 1) * 16;

    load_tile_async<64>(sb + 0, gAh, bm, 0, tid, KPAD2 / 8);
    load_tile_async<128>(sb + TILE_A2, gBh, 0, 0, tid, KPAD2 / 8);
    CP_COMMIT();

    for (int c = 0; c < NCHUNKS2; ++c) {
        const uint32_t cur = sb + (uint32_t)(c & 1) * STAGE2;
        if (c + 1 < NCHUNKS2) {
            const uint32_t nxt = sb + (uint32_t)((c + 1) & 1) * STAGE2;
            load_tile_async<64>(nxt + 0, gAh, bm, c + 1, tid, KPAD2 / 8);
            load_tile_async<128>(nxt + TILE_A2, gBh, 0, c + 1, tid, KPAD2 / 8);
            CP_COMMIT();
            CP_WAIT(1);
        } else {
            CP_WAIT(0);
        }
        __syncthreads();

        const uint32_t sAh = cur + 0;
        const uint32_t sBh = cur + TILE_A2;

#pragma unroll
        for (int kk = 0; kk < 4; ++kk) {
            const int kbyte = kk * 32;
            uint32_t Ah[2][4];
#pragma unroll
            for (int mb = 0; mb < 2; ++mb) {
                const int row = wm * 32 + mb * 16 + a_row;
                ldsm_x4(Ah[mb], swz(sAh, row, kbyte + a_kb));
            }
            uint32_t Bh[4][2];
#pragma unroll
            for (int pb = 0; pb < 2; ++pb) {
                const int row = wn * 32 + pb * 16 + b_row;
                uint32_t t[4];
                ldsm_x4(t, swz(sBh, row, kbyte + b_kb));
                Bh[2 * pb][0] = t[0]; Bh[2 * pb][1] = t[1];
                Bh[2 * pb + 1][0] = t[2]; Bh[2 * pb + 1][1] = t[3];
            }
#pragma unroll
            for (int mb = 0; mb < 2; ++mb)
#pragma unroll
                for (int nb = 0; nb < 4; ++nb)
                    mma_f16(acc[mb][nb], Ah[mb], Bh[nb]);
        }
        __syncthreads();
    }

    // epilogue: bias, write f32 out, guard n < 100
#pragma unroll
    for (int mb = 0; mb < 2; ++mb) {
        const int m0 = bm + wm * 32 + mb * 16 + (lane >> 2);
#pragma unroll
        for (int nb = 0; nb < 4; ++nb) {
            const int n0 = wn * 32 + nb * 8 + 2 * (lane & 3);
            if (n0 < OUTDIM) {
                const float b0 = __ldg(&bias[n0]);
                const float b1 = __ldg(&bias[n0 + 1]);
                float2 v0, v1;
                v0.x = acc[mb][nb][0] + b0;
                v0.y = acc[mb][nb][1] + b1;
                v1.x = acc[mb][nb][2] + b0;
                v1.y = acc[mb][nb][3] + b1;
                *reinterpret_cast<float2*>(C + (size_t)m0 * OUTDIM + n0)       = v0;
                *reinterpret_cast<float2*>(C + (size_t)(m0 + 8) * OUTDIM + n0) = v1;
            }
        }
    }
}

// ---------------------------------------------------------------------------
// launch (single stream, plain captured launches — R14 structure)
// ---------------------------------------------------------------------------
extern "C" void kernel_launch(void* const* d_in, const int* in_sizes, int n_in,
                              void* d_out, int out_size) {
    const float* inputs = (const float*)d_in[0];      // [8192, 978] f32
    const int*   edges  = (const int*)d_in[1];        // [2, E] int32
    const float* gw     = (const float*)d_in[2];      // [1,1]
    const float* gb     = (const float*)d_in[3];      // [1]
    const float* W1     = (const float*)d_in[4];      // [978, 2048]
    const float* b1     = (const float*)d_in[5];      // [2048]
    const float* W2     = (const float*)d_in[6];      // [2048, 100]
    const float* b2     = (const float*)d_in[7];      // [100]
    float*       out    = (float*)d_out;              // [8192, 100]

    const long long E = (long long)in_sizes[1] / 2;   // 20,000,000

    cudaFuncSetAttribute(tc_gemm1_kernel,
                         cudaFuncAttributeMaxDynamicSharedMemorySize, SMEM_TOTAL_G);
    cudaFuncSetAttribute(tc_gemm2_kernel,
                         cudaFuncAttributeMaxDynamicSharedMemorySize, SMEM_TOTAL_G2);

    // 1) zero accumulator
    {
        int n4 = NNODES / 4;
        zero_agg_kernel<<<(n4 + 255) / 256, 256>>>();
    }
    // 2) edge scatter (8 edges/thread)
    {
        long long threads_needed = (E + 7) / 8;
        int blocks = (int)((threads_needed + 255) / 256);
        scatter_kernel<<<blocks, 256>>>(edges, inputs, gw, E);
    }
    // 3) h = relu(agg + b) -> fp16 (half2)
    {
        size_t n = (size_t)BATCH * KPAD / 2;
        convA_kernel<<<(int)((n + 255) / 256), 256>>>(gb);
    }
    // 4) W1^T and W2^T in one launch
    {
        dim3 blk(32, 8);
        transpose_both_kernel<<<NB1 + NB2, blk>>>(W1, W2);
    }
    // 5) h1 = relu(h @ W1 + b1) -> fp16 (fused epilogue)
    {
        dim3 grid(H1DIM / 128, BATCH / 128);
        tc_gemm1_kernel<<<grid, 256, SMEM_TOTAL_G>>>(b1);
    }
    // 6) out = h1 @ W2 + b2 on HMMA (single-pass)
    {
        dim3 grid(1, BATCH / 64);
        tc_gemm2_kernel<<<grid, 256, SMEM_TOTAL_G2>>>(b2, out);
    }
}